// round 15
// baseline (speedup 1.0000x reference)
#include <cuda_runtime.h>
#include <cstdint>
#include <math.h>

// Problem constants
#define BB 4
#define SS 4096
#define NN 4096
#define CC 32

#define KCH 64               // k (n) per staged chunk (per half)
#define NCH 32               // chunks per half (covers 2048 n each)
#define STILES (SS / 128)    // 32 s-tiles of 128 rows
#define NTHREADS 1024        // 32 warps: 2 kh x 2 reim x 8 row-groups
#define XST 36               // xsh row stride in u32 (32 k-pairs + 4 pad)
#define XBUF (CC * XST)      // u32 per buffer (1152)

typedef unsigned long long ull;

// ---- packed f32x2 helpers ----
__device__ __forceinline__ ull pk2(float lo, float hi) {
    ull r; asm("mov.b64 %0, {%1, %2};" : "=l"(r) : "f"(lo), "f"(hi)); return r;
}
__device__ __forceinline__ float2 upk2(ull v) {
    float lo, hi; asm("mov.b64 {%0, %1}, %2;" : "=f"(lo), "=f"(hi) : "l"(v));
    return make_float2(lo, hi);
}
__device__ __forceinline__ ull fma2n(ull a, ull b, ull c) {
    ull r; asm("fma.rn.f32x2 %0, %1, %2, %3;" : "=l"(r) : "l"(a), "l"(b), "l"(c)); return r;
}
__device__ __forceinline__ ull mul2(ull a, ull b) {
    ull r; asm("mul.rn.f32x2 %0, %1, %2;" : "=l"(r) : "l"(a), "l"(b)); return r;
}
__device__ __forceinline__ ull add2(ull a, ull b) {
    ull r; asm("add.rn.f32x2 %0, %1, %2;" : "=l"(r) : "l"(a), "l"(b)); return r;
}
__device__ __forceinline__ uint32_t f2h2(float lo, float hi) {
    uint32_t r; asm("cvt.rn.f16x2.f32 %0, %1, %2;" : "=r"(r) : "f"(hi), "f"(lo)); return r;
}

// m16n8k16 fp16 HMMA, D(f32) += A(f16)*B(f16)
__device__ __forceinline__ void mma16(float d[4], const uint32_t a[4],
                                      uint32_t b0, uint32_t b1) {
    asm volatile(
        "mma.sync.aligned.m16n8k16.row.col.f32.f16.f16.f32 "
        "{%0,%1,%2,%3}, {%4,%5,%6,%7}, {%8,%9}, {%0,%1,%2,%3};"
        : "+f"(d[0]), "+f"(d[1]), "+f"(d[2]), "+f"(d[3])
        : "r"(a[0]), "r"(a[1]), "r"(a[2]), "r"(a[3]), "r"(b0), "r"(b1));
}

__device__ __forceinline__ void ldsm4(uint32_t& r0, uint32_t& r1,
                                      uint32_t& r2, uint32_t& r3, uint32_t addr) {
    asm volatile("ldmatrix.sync.aligned.m8n8.x4.shared.b16 {%0,%1,%2,%3}, [%4];"
        : "=r"(r0), "=r"(r1), "=r"(r2), "=r"(r3) : "r"(addr));
}

// half barrier: named barrier (1+kh), 512 threads
__device__ __forceinline__ void half_bar(int kh) {
    asm volatile("bar.sync %0, %1;" :: "r"(1 + kh), "r"(512) : "memory");
}

// Range reduction: phase = k*2pi + r, |r| <= pi
#define INV2PI   0.15915493667125701904f
#define TWOPI_A  6.28318548202514648438f
#define TWOPI_B  (-1.74845552749343265e-7f)
#define MAGIC    12582912.0f    /* 1.5 * 2^23 */
#define ROWK     (-1.5339807878856412e-3f)   /* fl(-2*pi/4096) */

__global__ __launch_bounds__(NTHREADS, 1)
void fudft_hmma(const float* __restrict__ x,
                const float* __restrict__ t,
                const float* __restrict__ freqs,
                float* __restrict__ out) {
    // cols_sm doubles as the accumulator exchange buffer in the epilogue (16 KB)
    __shared__ __align__(16) float cols_sm[NN];
    // per-half, double-buffered X^T chunk: [half][buf][c][kpair] f16x2
    __shared__ __align__(16) uint32_t xsh[2 * 2 * XBUF];   // 18.4 KB

    const int tid  = threadIdx.x;
    const int wid  = tid >> 5;
    const int lane = tid & 31;
    const int kh   = wid >> 4;          // K-half 0/1
    const int reim = (wid >> 3) & 1;    // 0 = Re (cos), 1 = Im (sin)
    const int wg   = wid & 7;           // row group 0..7 (16 rows each)
    const int g    = lane >> 2;         // 0..7
    const int qid  = lane & 3;          // 0..3
    const int htid = tid & 511;         // thread id within half

    const int bx    = blockIdx.x;       // 0..127
    const int stile = bx & (STILES - 1);
    const int b     = bx >> 5;

    // ---- stage cols for the whole batch row (once, all 1024 threads) ----
    {
        const float4* t4 = (const float4*)(t + (size_t)b * NN);
        float4 v = t4[tid];
        v.x *= 4095.0f; v.y *= 4095.0f; v.z *= 4095.0f; v.w *= 4095.0f;
        ((float4*)cols_sm)[tid] = v;
    }

    // ---- per-thread row frequencies (A-fragment rows g and g+8) ----
    const int s_base = stile * 128 + wg * 16;
    const float rs0 = (freqs[s_base + g]     * 4095.0f) * ROWK;
    const float rs1 = (freqs[s_base + g + 8] * 4095.0f) * ROWK;
    const ull rs0_2   = pk2(rs0, rs0);
    const ull rs1_2   = pk2(rs1, rs1);
    const ull inv2pi2 = pk2(INV2PI, INV2PI);
    const ull magic2  = pk2(MAGIC, MAGIC);
    const ull nmag2   = pk2(-MAGIC, -MAGIC);
    const ull nA2     = pk2(-TWOPI_A, -TWOPI_A);
    const ull nB2     = pk2(-TWOPI_B, -TWOPI_B);

    // accumulators: 4 n-tiles x 4 (Re OR Im only)
    float acc[4][4];
#pragma unroll
    for (int nt = 0; nt < 4; ++nt)
#pragma unroll
        for (int j = 0; j < 4; ++j) acc[nt][j] = 0.0f;

    // ---- ldmatrix per-lane row addressing (within this half's buffers) ----
    const uint32_t xsh_base = (uint32_t)__cvta_generic_to_shared(xsh)
                            + (uint32_t)(kh * 2 * XBUF) * 4u;
    const int lm_m  = lane >> 3;
    const int lm_c  = 8 * (lm_m >> 1) + (lane & 7);
    const uint32_t lm_i0 = (uint32_t)(lm_c * XST + 4 * (lm_m & 1));

    // ---- staging decomposition (per half: 512 threads, 1 float4 each) ----
    const int base_n = kh * 2048;
    const float4* xg = (const float4*)(x + (size_t)b * NN * CC);
    const int kk   = htid >> 3;       // 0..63
    const int aa   = htid & 7;        // c block: c0 = 4*aa
    const int kodd = kk & 1;
    const int kp   = kk >> 1;         // k-pair col 0..31
    const int c0   = aa * 4;
    uint32_t* const myxsh = xsh + kh * 2 * XBUF;

    __syncthreads();   // cols ready

    // stage chunk 0 into buffer 0
    {
        float4 v = xg[base_n * 8 + htid];
        uint32_t q0 = f2h2(v.x, v.y);
        uint32_t q1 = f2h2(v.z, v.w);
        uint32_t s0 = __shfl_xor_sync(0xffffffffu, q0, 8);
        uint32_t s1 = __shfl_xor_sync(0xffffffffu, q1, 8);
        if (!kodd) {
            myxsh[c0 * XST + kp]       = __byte_perm(q0, s0, 0x5410);
            myxsh[(c0 + 1) * XST + kp] = __byte_perm(q0, s0, 0x7632);
        } else {
            myxsh[(c0 + 2) * XST + kp] = __byte_perm(s1, q1, 0x5410);
            myxsh[(c0 + 3) * XST + kp] = __byte_perm(s1, q1, 0x7632);
        }
    }
    half_bar(kh);

#pragma unroll 1
    for (int st = 0; st < NCH; ++st) {
        const int p = st & 1;
        const int n0 = base_n + st * KCH;

        // stage chunk st+1 into other buffer (LDG early; 8 warps/SMSP hide it)
        if (st < NCH - 1) {
            float4 v = xg[(n0 + KCH) * 8 + htid];
            uint32_t q0 = f2h2(v.x, v.y);
            uint32_t q1 = f2h2(v.z, v.w);
            uint32_t s0 = __shfl_xor_sync(0xffffffffu, q0, 8);
            uint32_t s1 = __shfl_xor_sync(0xffffffffu, q1, 8);
            uint32_t* dst = myxsh + (p ? 0 : XBUF);
            if (!kodd) {
                dst[c0 * XST + kp]       = __byte_perm(q0, s0, 0x5410);
                dst[(c0 + 1) * XST + kp] = __byte_perm(q0, s0, 0x7632);
            } else {
                dst[(c0 + 2) * XST + kp] = __byte_perm(s1, q1, 0x5410);
                dst[(c0 + 3) * XST + kp] = __byte_perm(s1, q1, 0x7632);
            }
        }

        const float* cols_loc = cols_sm + n0;
        uint32_t aA = xsh_base + (uint32_t)(p * XBUF + lm_i0) * 4u;
        uint32_t aB = aA + 16 * XST * 4;

#pragma unroll
        for (int ks2 = 0; ks2 < 4; ++ks2) {
            const int k0 = ks2 * 16;

            uint32_t bq[8];
            ldsm4(bq[0], bq[1], bq[2], bq[3], aA);
            ldsm4(bq[4], bq[5], bq[6], bq[7], aB);
            aA += 32; aB += 32;

            const ull cA = *(const ull*)(cols_loc + k0 + 2 * qid);
            const ull cB = *(const ull*)(cols_loc + k0 + 2 * qid + 8);

            ull p00 = mul2(rs0_2, cA), p01 = mul2(rs0_2, cB);
            ull p10 = mul2(rs1_2, cA), p11 = mul2(rs1_2, cB);
            ull m00 = fma2n(p00, inv2pi2, magic2), m01 = fma2n(p01, inv2pi2, magic2);
            ull m10 = fma2n(p10, inv2pi2, magic2), m11 = fma2n(p11, inv2pi2, magic2);
            ull k00 = add2(m00, nmag2), k01 = add2(m01, nmag2);
            ull k10 = add2(m10, nmag2), k11 = add2(m11, nmag2);
            ull r00 = fma2n(k00, nA2, p00); r00 = fma2n(k00, nB2, r00);
            ull r01 = fma2n(k01, nA2, p01); r01 = fma2n(k01, nB2, r01);
            ull r10 = fma2n(k10, nA2, p10); r10 = fma2n(k10, nB2, r10);
            ull r11 = fma2n(k11, nA2, p11); r11 = fma2n(k11, nB2, r11);
            const float2 f00 = upk2(r00), f01 = upk2(r01);
            const float2 f10 = upk2(r10), f11 = upk2(r11);

            // one trig function per warp (Re warps: cos; Im warps: sin)
            uint32_t a[4];
            if (reim == 0) {
                a[0] = f2h2(__cosf(f00.x), __cosf(f00.y));
                a[1] = f2h2(__cosf(f10.x), __cosf(f10.y));
                a[2] = f2h2(__cosf(f01.x), __cosf(f01.y));
                a[3] = f2h2(__cosf(f11.x), __cosf(f11.y));
            } else {
                a[0] = f2h2(__sinf(f00.x), __sinf(f00.y));
                a[1] = f2h2(__sinf(f10.x), __sinf(f10.y));
                a[2] = f2h2(__sinf(f01.x), __sinf(f01.y));
                a[3] = f2h2(__sinf(f11.x), __sinf(f11.y));
            }

#pragma unroll
            for (int nt = 0; nt < 4; ++nt)
                mma16(acc[nt], a, bq[2 * nt], bq[2 * nt + 1]);
        }
        half_bar(kh);
    }

    // ---- epilogue: combine (kh, reim) groups through cols_sm, 4 nt phases ----
    __syncthreads();   // all compute done
    const int grp = kh * 2 + reim;     // 0 = writer of output
    const int s0g = s_base + g;
    const int s1g = s0g + 8;
    const bool z0 = (s0g == 0) || (s0g == SS - 1);
    const bool z1 = (s1g == 0) || (s1g == SS - 1);
    float* o0 = out + ((size_t)b * SS + s0g) * CC;
    float* o1 = out + ((size_t)b * SS + s1g) * CC;
    float4* ex = (float4*)cols_sm;

#pragma unroll
    for (int nt = 0; nt < 4; ++nt) {
        if (grp != 0)
            ex[((grp - 1) * 8 + wg) * 32 + lane] = *(const float4*)acc[nt];
        __syncthreads();
        if (grp == 0) {
            float4 im0 = ex[(0 * 8 + wg) * 32 + lane];   // kh0, sin
            float4 re1 = ex[(1 * 8 + wg) * 32 + lane];   // kh1, cos
            float4 im1 = ex[(2 * 8 + wg) * 32 + lane];   // kh1, sin
            float re0v = acc[nt][0] + re1.x, im0v = im0.x + im1.x;
            float re1v = acc[nt][1] + re1.y, im1v = im0.y + im1.y;
            float re2v = acc[nt][2] + re1.z, im2v = im0.z + im1.z;
            float re3v = acc[nt][3] + re1.w, im3v = im0.w + im1.w;
            const int c = nt * 8 + 2 * qid;
            float2 w;
            w.x = z0 ? 0.0f : sqrtf(fmaf(re0v, re0v, im0v * im0v)) * 0.015625f;
            w.y = z0 ? 0.0f : sqrtf(fmaf(re1v, re1v, im1v * im1v)) * 0.015625f;
            *(float2*)(o0 + c) = w;
            w.x = z1 ? 0.0f : sqrtf(fmaf(re2v, re2v, im2v * im2v)) * 0.015625f;
            w.y = z1 ? 0.0f : sqrtf(fmaf(re3v, re3v, im3v * im3v)) * 0.015625f;
            *(float2*)(o1 + c) = w;
        }
        if (nt < 3) __syncthreads();
    }
}

extern "C" void kernel_launch(void* const* d_in, const int* in_sizes, int n_in,
                              void* d_out, int out_size) {
    const float* x     = (const float*)d_in[0];   // [4,4096,32]
    const float* t     = (const float*)d_in[1];   // [4,4096]
    const float* freqs = (const float*)d_in[2];   // [4096]
    float* out = (float*)d_out;                   // [4,4096,32]

    fudft_hmma<<<BB * STILES, NTHREADS>>>(x, t, freqs, out);
}

// round 16
// speedup vs baseline: 1.1821x; 1.1821x over previous
#include <cuda_runtime.h>
#include <cstdint>
#include <math.h>

// Problem constants
#define BB 4
#define SS 4096
#define NN 4096
#define CC 32

#define KCH 32               // n per staged chunk (per K-quarter group)
#define NCH 32               // chunks per group (covers 1024 n each)
#define STILES (SS / 128)    // 32 s-tiles of 128 rows
#define NTHREADS 1024        // 32 warps: 4 K-quarters x 8 row-groups
#define XST 20               // xsh row stride in u32 (16 k-pairs + 4 pad)
#define QBUF (CC * XST)      // u32 per buffer (640)

// Range reduction: phase = k*2pi + r, |r| <= pi  (immediate-operand scalar path)
#define INV2PI   0.15915493667125701904f
#define TWOPI_A  6.28318548202514648438f
#define TWOPI_B  (-1.74845552749343265e-7f)
#define MAGIC    12582912.0f    /* 1.5 * 2^23 */
#define ROWK     (-1.5339807878856412e-3f)   /* fl(-2*pi/4096) */

// pack two f32 -> f16x2 (RNE). lo = low half of result.
__device__ __forceinline__ uint32_t f2h2(float lo, float hi) {
    uint32_t r; asm("cvt.rn.f16x2.f32 %0, %1, %2;" : "=r"(r) : "f"(hi), "f"(lo)); return r;
}

// m16n8k16 fp16 HMMA, D(f32) += A(f16)*B(f16)
__device__ __forceinline__ void mma16(float d[4], const uint32_t a[4],
                                      uint32_t b0, uint32_t b1) {
    asm volatile(
        "mma.sync.aligned.m16n8k16.row.col.f32.f16.f16.f32 "
        "{%0,%1,%2,%3}, {%4,%5,%6,%7}, {%8,%9}, {%0,%1,%2,%3};"
        : "+f"(d[0]), "+f"(d[1]), "+f"(d[2]), "+f"(d[3])
        : "r"(a[0]), "r"(a[1]), "r"(a[2]), "r"(a[3]), "r"(b0), "r"(b1));
}

__device__ __forceinline__ void ldsm4(uint32_t& r0, uint32_t& r1,
                                      uint32_t& r2, uint32_t& r3, uint32_t addr) {
    asm volatile("ldmatrix.sync.aligned.m8n8.x4.shared.b16 {%0,%1,%2,%3}, [%4];"
        : "=r"(r0), "=r"(r1), "=r"(r2), "=r"(r3) : "r"(addr));
}

// group barrier: named barrier (1+kq), 256 threads
__device__ __forceinline__ void grp_bar(int kq) {
    asm volatile("bar.sync %0, %1;" :: "r"(1 + kq), "r"(256) : "memory");
}

// scalar reduce + sincos phase: r = phase mod 2pi in [-pi, pi]
__device__ __forceinline__ float red2pi(float rs, float c) {
    float ph = rs * c;
    float m  = fmaf(ph, INV2PI, MAGIC);
    float kf = m - MAGIC;
    float r  = fmaf(kf, -TWOPI_A, ph);
    return fmaf(kf, -TWOPI_B, r);
}

__global__ __launch_bounds__(NTHREADS, 1)
void fudft_hmma(const float* __restrict__ x,
                const float* __restrict__ t,
                const float* __restrict__ freqs,
                float* __restrict__ out) {
    // cols_sm doubles as the Re exchange buffer in the epilogue (16 KB)
    __shared__ __align__(16) float cols_sm[NN];
    // per-group, double-buffered X^T chunk: [kq][buf][c][kpair] f16x2 (20 KB)
    // doubles as the Im exchange buffer in the epilogue
    __shared__ __align__(16) uint32_t xsh[4 * 2 * QBUF];

    const int tid  = threadIdx.x;
    const int wid  = tid >> 5;
    const int lane = tid & 31;
    const int kq   = wid >> 3;          // K-quarter 0..3
    const int wg   = wid & 7;           // row group 0..7 (16 rows each)
    const int g    = lane >> 2;         // 0..7
    const int qid  = lane & 3;          // 0..3
    const int htid = tid & 255;         // thread id within group

    const int bx    = blockIdx.x;       // 0..127
    const int stile = bx & (STILES - 1);
    const int b     = bx >> 5;

    // ---- stage cols for the whole batch row (once, all 1024 threads) ----
    {
        const float4* t4 = (const float4*)(t + (size_t)b * NN);
        float4 v = t4[tid];
        v.x *= 4095.0f; v.y *= 4095.0f; v.z *= 4095.0f; v.w *= 4095.0f;
        ((float4*)cols_sm)[tid] = v;
    }

    // ---- per-thread row frequencies (A-fragment rows g and g+8) ----
    const int s_base = stile * 128 + wg * 16;
    const float rs0 = (freqs[s_base + g]     * 4095.0f) * ROWK;
    const float rs1 = (freqs[s_base + g + 8] * 4095.0f) * ROWK;

    float accre[4][4], accim[4][4];
#pragma unroll
    for (int nt = 0; nt < 4; ++nt)
#pragma unroll
        for (int j = 0; j < 4; ++j) { accre[nt][j] = 0.0f; accim[nt][j] = 0.0f; }

    // ---- ldmatrix per-lane row addressing (within this group's buffers) ----
    const uint32_t xsh_base = (uint32_t)__cvta_generic_to_shared(xsh)
                            + (uint32_t)(kq * 2 * QBUF) * 4u;
    const int lm_m  = lane >> 3;
    const int lm_c  = 8 * (lm_m >> 1) + (lane & 7);
    const uint32_t lm_i0 = (uint32_t)(lm_c * XST + 4 * (lm_m & 1));

    // ---- staging decomposition (per group: 256 threads, 1 float4/chunk) ----
    const int base_n = kq * 1024;
    const float4* xg = (const float4*)(x + (size_t)b * NN * CC);
    const int nn   = htid >> 3;       // 0..31 (n within chunk)
    const int aa   = htid & 7;        // c block: c0 = 4*aa
    const int kodd = nn & 1;
    const int kp   = nn >> 1;         // k-pair col 0..15
    const int c0   = aa * 4;
    uint32_t* const myxsh = xsh + kq * 2 * QBUF;

    __syncthreads();   // cols ready

    // stage chunk 0 into buffer 0
    {
        float4 v = xg[base_n * 8 + htid];
        uint32_t q0 = f2h2(v.x, v.y);
        uint32_t q1 = f2h2(v.z, v.w);
        uint32_t s0 = __shfl_xor_sync(0xffffffffu, q0, 8);
        uint32_t s1 = __shfl_xor_sync(0xffffffffu, q1, 8);
        if (!kodd) {
            myxsh[c0 * XST + kp]       = __byte_perm(q0, s0, 0x5410);
            myxsh[(c0 + 1) * XST + kp] = __byte_perm(q0, s0, 0x7632);
        } else {
            myxsh[(c0 + 2) * XST + kp] = __byte_perm(s1, q1, 0x5410);
            myxsh[(c0 + 3) * XST + kp] = __byte_perm(s1, q1, 0x7632);
        }
    }
    grp_bar(kq);

#pragma unroll 1
    for (int st = 0; st < NCH; ++st) {
        const int p = st & 1;
        const int n0 = base_n + st * KCH;

        // stage chunk st+1 into other buffer (LDG early; 8 warps/SMSP hide it)
        if (st < NCH - 1) {
            float4 v = xg[(n0 + KCH) * 8 + htid];
            uint32_t q0 = f2h2(v.x, v.y);
            uint32_t q1 = f2h2(v.z, v.w);
            uint32_t s0 = __shfl_xor_sync(0xffffffffu, q0, 8);
            uint32_t s1 = __shfl_xor_sync(0xffffffffu, q1, 8);
            uint32_t* dst = myxsh + (p ? 0 : QBUF);
            if (!kodd) {
                dst[c0 * XST + kp]       = __byte_perm(q0, s0, 0x5410);
                dst[(c0 + 1) * XST + kp] = __byte_perm(q0, s0, 0x7632);
            } else {
                dst[(c0 + 2) * XST + kp] = __byte_perm(s1, q1, 0x5410);
                dst[(c0 + 3) * XST + kp] = __byte_perm(s1, q1, 0x7632);
            }
        }

        uint32_t aA = xsh_base + (uint32_t)(p * QBUF + lm_i0) * 4u;
        uint32_t aB = aA + 16 * XST * 4;

        // 2 k16-steps over this 32-n chunk
#pragma unroll
        for (int ks = 0; ks < 2; ++ks) {
            uint32_t bq[8];
            ldsm4(bq[0], bq[1], bq[2], bq[3], aA);
            ldsm4(bq[4], bq[5], bq[6], bq[7], aB);
            aA += 32; aB += 32;

            const float* cl = cols_sm + n0 + ks * 16 + 2 * qid;
            const float2 ca = *(const float2*)cl;        // cols k0+2qid, +1
            const float2 cb = *(const float2*)(cl + 8);  // cols k0+2qid+8, +9

            // 8 scalar reductions (immediate-coefficient FFMA chain)
            float rA00 = red2pi(rs0, ca.x), rA01 = red2pi(rs0, ca.y);
            float rA10 = red2pi(rs1, ca.x), rA11 = red2pi(rs1, ca.y);
            float rB00 = red2pi(rs0, cb.x), rB01 = red2pi(rs0, cb.y);
            float rB10 = red2pi(rs1, cb.x), rB11 = red2pi(rs1, cb.y);

            uint32_t ac[4], as_[4];
            ac[0]  = f2h2(__cosf(rA00), __cosf(rA01));
            as_[0] = f2h2(__sinf(rA00), __sinf(rA01));
            ac[1]  = f2h2(__cosf(rA10), __cosf(rA11));
            as_[1] = f2h2(__sinf(rA10), __sinf(rA11));
            ac[2]  = f2h2(__cosf(rB00), __cosf(rB01));
            as_[2] = f2h2(__sinf(rB00), __sinf(rB01));
            ac[3]  = f2h2(__cosf(rB10), __cosf(rB11));
            as_[3] = f2h2(__sinf(rB10), __sinf(rB11));

#pragma unroll
            for (int nt = 0; nt < 4; ++nt) {
                mma16(accre[nt], ac,  bq[2 * nt], bq[2 * nt + 1]);
                mma16(accim[nt], as_, bq[2 * nt], bq[2 * nt + 1]);
            }
        }
        grp_bar(kq);
    }

    // ---- epilogue: 4-way K merge; Re via cols_sm, Im via xsh; 4 nt phases ----
    __syncthreads();   // all groups done
    const int s0g = s_base + g;
    const int s1g = s0g + 8;
    const bool z0 = (s0g == 0) || (s0g == SS - 1);
    const bool z1 = (s1g == 0) || (s1g == SS - 1);
    float* o0 = out + ((size_t)b * SS + s0g) * CC;
    float* o1 = out + ((size_t)b * SS + s1g) * CC;
    float4* exr = (float4*)cols_sm;
    float4* exi = (float4*)xsh;

#pragma unroll
    for (int nt = 0; nt < 4; ++nt) {
        if (kq != 0) {
            const int slot = ((kq - 1) * 8 + wg) * 32 + lane;
            exr[slot] = *(const float4*)accre[nt];
            exi[slot] = *(const float4*)accim[nt];
        }
        __syncthreads();
        if (kq == 0) {
            const int s1 = (0 * 8 + wg) * 32 + lane;
            const int s2 = (1 * 8 + wg) * 32 + lane;
            const int s3 = (2 * 8 + wg) * 32 + lane;
            float4 r1 = exr[s1], r2 = exr[s2], r3 = exr[s3];
            float4 i1 = exi[s1], i2 = exi[s2], i3 = exi[s3];
            float re0 = accre[nt][0] + r1.x + r2.x + r3.x;
            float re1 = accre[nt][1] + r1.y + r2.y + r3.y;
            float re2 = accre[nt][2] + r1.z + r2.z + r3.z;
            float re3 = accre[nt][3] + r1.w + r2.w + r3.w;
            float im0 = accim[nt][0] + i1.x + i2.x + i3.x;
            float im1 = accim[nt][1] + i1.y + i2.y + i3.y;
            float im2 = accim[nt][2] + i1.z + i2.z + i3.z;
            float im3 = accim[nt][3] + i1.w + i2.w + i3.w;
            const int c = nt * 8 + 2 * qid;
            float2 w;
            w.x = z0 ? 0.0f : sqrtf(fmaf(re0, re0, im0 * im0)) * 0.015625f;
            w.y = z0 ? 0.0f : sqrtf(fmaf(re1, re1, im1 * im1)) * 0.015625f;
            *(float2*)(o0 + c) = w;
            w.x = z1 ? 0.0f : sqrtf(fmaf(re2, re2, im2 * im2)) * 0.015625f;
            w.y = z1 ? 0.0f : sqrtf(fmaf(re3, re3, im3 * im3)) * 0.015625f;
            *(float2*)(o1 + c) = w;
        }
        if (nt < 3) __syncthreads();
    }
}

extern "C" void kernel_launch(void* const* d_in, const int* in_sizes, int n_in,
                              void* d_out, int out_size) {
    const float* x     = (const float*)d_in[0];   // [4,4096,32]
    const float* t     = (const float*)d_in[1];   // [4,4096]
    const float* freqs = (const float*)d_in[2];   // [4096]
    float* out = (float*)d_out;                   // [4,4096,32]

    fudft_hmma<<<BB * STILES, NTHREADS>>>(x, t, freqs, out);
}

// round 17
// speedup vs baseline: 1.2276x; 1.0385x over previous
#include <cuda_runtime.h>
#include <cstdint>
#include <math.h>

// Problem constants
#define BB 4
#define SS 4096
#define NN 4096
#define CC 32

#define HN 2048              // n per staged half
#define STILES (SS / 128)    // 32 s-tiles of 128 rows
#define NTHREADS 512         // 16 warps: 2 K-groups x 8 row-groups
#define XSTRIDE 1028         // xbuf row stride in u32 (1024 kpairs + 4 pad; ==4 mod 32)
#define XHALF_U32 (CC * XSTRIDE)           // 32896 u32 = 131584 B
#define SMEM_COLS 16384                    // 4096 floats
#define SMEM_TOTAL (SMEM_COLS + XHALF_U32 * 4)   // 147968 B

typedef unsigned long long ull;

// ---- packed f32x2 helpers ----
__device__ __forceinline__ ull pk2(float lo, float hi) {
    ull r; asm("mov.b64 %0, {%1, %2};" : "=l"(r) : "f"(lo), "f"(hi)); return r;
}
__device__ __forceinline__ float2 upk2(ull v) {
    float lo, hi; asm("mov.b64 {%0, %1}, %2;" : "=f"(lo), "=f"(hi) : "l"(v));
    return make_float2(lo, hi);
}
__device__ __forceinline__ ull fma2n(ull a, ull b, ull c) {
    ull r; asm("fma.rn.f32x2 %0, %1, %2, %3;" : "=l"(r) : "l"(a), "l"(b), "l"(c)); return r;
}
__device__ __forceinline__ ull mul2(ull a, ull b) {
    ull r; asm("mul.rn.f32x2 %0, %1, %2;" : "=l"(r) : "l"(a), "l"(b)); return r;
}
__device__ __forceinline__ ull add2(ull a, ull b) {
    ull r; asm("add.rn.f32x2 %0, %1, %2;" : "=l"(r) : "l"(a), "l"(b)); return r;
}
__device__ __forceinline__ uint32_t f2h2(float lo, float hi) {
    uint32_t r; asm("cvt.rn.f16x2.f32 %0, %1, %2;" : "=r"(r) : "f"(hi), "f"(lo)); return r;
}

// m16n8k16 fp16 HMMA, D(f32) += A(f16)*B(f16)
__device__ __forceinline__ void mma16(float d[4], const uint32_t a[4],
                                      uint32_t b0, uint32_t b1) {
    asm volatile(
        "mma.sync.aligned.m16n8k16.row.col.f32.f16.f16.f32 "
        "{%0,%1,%2,%3}, {%4,%5,%6,%7}, {%8,%9}, {%0,%1,%2,%3};"
        : "+f"(d[0]), "+f"(d[1]), "+f"(d[2]), "+f"(d[3])
        : "r"(a[0]), "r"(a[1]), "r"(a[2]), "r"(a[3]), "r"(b0), "r"(b1));
}

__device__ __forceinline__ void ldsm4(uint32_t& r0, uint32_t& r1,
                                      uint32_t& r2, uint32_t& r3, uint32_t addr) {
    asm volatile("ldmatrix.sync.aligned.m8n8.x4.shared.b16 {%0,%1,%2,%3}, [%4];"
        : "=r"(r0), "=r"(r1), "=r"(r2), "=r"(r3) : "r"(addr));
}

// Range reduction: phase = k*2pi + r, |r| <= pi
#define INV2PI   0.15915493667125701904f
#define TWOPI_A  6.28318548202514648438f
#define TWOPI_B  (-1.74845552749343265e-7f)
#define MAGIC    12582912.0f    /* 1.5 * 2^23 */
#define ROWK     (-1.5339807878856412e-3f)   /* fl(-2*pi/4096) */

__global__ __launch_bounds__(NTHREADS, 1)
void fudft_hmma(const float* __restrict__ x,
                const float* __restrict__ t,
                const float* __restrict__ freqs,
                float* __restrict__ out) {
    extern __shared__ __align__(16) unsigned char smem[];
    float*    cols_sm = (float*)smem;                       // 16 KB; epilogue reuse
    uint32_t* xbuf    = (uint32_t*)(smem + SMEM_COLS);      // 131.6 KB

    const int tid  = threadIdx.x;
    const int wid  = tid >> 5;
    const int lane = tid & 31;
    const int wg   = wid & 7;       // row group 0..7 (16 rows each)
    const int kq   = wid >> 3;      // K-group 0/1 (quarter of n per half)
    const int g    = lane >> 2;     // 0..7
    const int qid  = lane & 3;      // 0..3

    const int bx    = blockIdx.x;   // 0..127
    const int stile = bx & (STILES - 1);
    const int b     = bx >> 5;

    // ---- stage cols for the whole batch row (once) ----
    {
        const float4* t4 = (const float4*)(t + (size_t)b * NN);
        float4* c4 = (float4*)cols_sm;
#pragma unroll
        for (int r = 0; r < 2; ++r) {
            float4 v = t4[tid + NTHREADS * r];
            v.x *= 4095.0f; v.y *= 4095.0f; v.z *= 4095.0f; v.w *= 4095.0f;
            c4[tid + NTHREADS * r] = v;
        }
    }

    // ---- per-thread row frequencies (A-fragment rows g and g+8) ----
    const int s_base = stile * 128 + wg * 16;
    const float rs0 = (freqs[s_base + g]     * 4095.0f) * ROWK;
    const float rs1 = (freqs[s_base + g + 8] * 4095.0f) * ROWK;
    const ull rs0_2   = pk2(rs0, rs0);
    const ull rs1_2   = pk2(rs1, rs1);
    const ull inv2pi2 = pk2(INV2PI, INV2PI);
    const ull magic2  = pk2(MAGIC, MAGIC);
    const ull nmag2   = pk2(-MAGIC, -MAGIC);
    const ull nA2     = pk2(-TWOPI_A, -TWOPI_A);
    const ull nB2     = pk2(-TWOPI_B, -TWOPI_B);

    float dre[4][4], dim[4][4];
#pragma unroll
    for (int nt = 0; nt < 4; ++nt)
#pragma unroll
        for (int j = 0; j < 4; ++j) { dre[nt][j] = 0.0f; dim[nt][j] = 0.0f; }

    // ---- ldmatrix per-lane row addressing ----
    const uint32_t xbuf_base = (uint32_t)__cvta_generic_to_shared(xbuf);
    const int lm_m  = lane >> 3;
    const int lm_c  = 8 * (lm_m >> 1) + (lane & 7);
    const uint32_t lm_i0 = (uint32_t)(lm_c * XSTRIDE + 4 * (lm_m & 1) + kq * 512);

    const float4* xg = (const float4*)(x + (size_t)b * NN * CC);

#pragma unroll 1
    for (int half = 0; half < 2; ++half) {
        // ---- stage this half: 2048n x 32c fp16, k-paired, 32 f4 per thread ----
        {
            const float4* xgh = xg + (size_t)half * HN * 8;
#pragma unroll 4
            for (int i = 0; i < 32; ++i) {
                const int idx = i * NTHREADS + tid;
                float4 v = xgh[idx];
                const int kk2  = idx >> 3;
                const int aa2  = idx & 7;
                const int kodd = kk2 & 1;
                const int kp   = kk2 >> 1;       // 0..1023
                const int c0   = aa2 * 4;
                uint32_t q0 = f2h2(v.x, v.y);
                uint32_t q1 = f2h2(v.z, v.w);
                uint32_t s0 = __shfl_xor_sync(0xffffffffu, q0, 8);
                uint32_t s1 = __shfl_xor_sync(0xffffffffu, q1, 8);
                if (!kodd) {
                    xbuf[c0 * XSTRIDE + kp]       = __byte_perm(q0, s0, 0x5410);
                    xbuf[(c0 + 1) * XSTRIDE + kp] = __byte_perm(q0, s0, 0x7632);
                } else {
                    xbuf[(c0 + 2) * XSTRIDE + kp] = __byte_perm(s1, q1, 0x5410);
                    xbuf[(c0 + 3) * XSTRIDE + kp] = __byte_perm(s1, q1, 0x7632);
                }
            }
        }
        __syncthreads();   // half staged (also covers cols on half 0)

        // ---- 64 k16-steps, NO barriers: warps free-run and desync ----
        const float* cols_c = cols_sm + half * HN + kq * 1024 + 2 * qid;
        uint32_t aA = xbuf_base + lm_i0 * 4u;
        uint32_t aB = aA + 16 * XSTRIDE * 4;

#pragma unroll 4
        for (int st = 0; st < 64; ++st) {
            uint32_t bq[8];
            ldsm4(bq[0], bq[1], bq[2], bq[3], aA);
            ldsm4(bq[4], bq[5], bq[6], bq[7], aB);
            aA += 32; aB += 32;

            const float* cl = cols_c + st * 16;
            const ull cA = *(const ull*)cl;
            const ull cB = *(const ull*)(cl + 8);

            ull p00 = mul2(rs0_2, cA), p01 = mul2(rs0_2, cB);
            ull p10 = mul2(rs1_2, cA), p11 = mul2(rs1_2, cB);
            ull m00 = fma2n(p00, inv2pi2, magic2), m01 = fma2n(p01, inv2pi2, magic2);
            ull m10 = fma2n(p10, inv2pi2, magic2), m11 = fma2n(p11, inv2pi2, magic2);
            ull k00 = add2(m00, nmag2), k01 = add2(m01, nmag2);
            ull k10 = add2(m10, nmag2), k11 = add2(m11, nmag2);
            ull r00 = fma2n(k00, nA2, p00); r00 = fma2n(k00, nB2, r00);
            ull r01 = fma2n(k01, nA2, p01); r01 = fma2n(k01, nB2, r01);
            ull r10 = fma2n(k10, nA2, p10); r10 = fma2n(k10, nB2, r10);
            ull r11 = fma2n(k11, nA2, p11); r11 = fma2n(k11, nB2, r11);
            const float2 f00 = upk2(r00), f01 = upk2(r01);
            const float2 f10 = upk2(r10), f11 = upk2(r11);

            uint32_t ac[4], as_[4];
            ac[0]  = f2h2(__cosf(f00.x), __cosf(f00.y));
            as_[0] = f2h2(__sinf(f00.x), __sinf(f00.y));
            ac[1]  = f2h2(__cosf(f10.x), __cosf(f10.y));
            as_[1] = f2h2(__sinf(f10.x), __sinf(f10.y));
            ac[2]  = f2h2(__cosf(f01.x), __cosf(f01.y));
            as_[2] = f2h2(__sinf(f01.x), __sinf(f01.y));
            ac[3]  = f2h2(__cosf(f11.x), __cosf(f11.y));
            as_[3] = f2h2(__sinf(f11.x), __sinf(f11.y));

#pragma unroll
            for (int nt = 0; nt < 4; ++nt) {
                mma16(dre[nt], ac,  bq[2 * nt], bq[2 * nt + 1]);
                mma16(dim[nt], as_, bq[2 * nt], bq[2 * nt + 1]);
            }
        }
        __syncthreads();   // all warps done reading xbuf before restaging
    }

    // ---- merge K-groups through cols_sm in 2 phases (nt pair per phase) ----
    const int s0g = s_base + g;
    const int s1g = s0g + 8;
    const bool z0 = (s0g == 0) || (s0g == SS - 1);
    const bool z1 = (s1g == 0) || (s1g == SS - 1);
    float* o0 = out + ((size_t)b * SS + s0g) * CC;
    float* o1 = out + ((size_t)b * SS + s1g) * CC;

#pragma unroll
    for (int p = 0; p < 2; ++p) {
        if (kq == 1) {
            float4* ex = (float4*)cols_sm;
#pragma unroll
            for (int j = 0; j < 2; ++j) {
                const int nt = 2 * p + j;
                ex[(wg * 4 + j * 2)     * 32 + lane] = *(const float4*)dre[nt];
                ex[(wg * 4 + j * 2 + 1) * 32 + lane] = *(const float4*)dim[nt];
            }
        }
        __syncthreads();
        if (kq == 0) {
            const float4* ex = (const float4*)cols_sm;
#pragma unroll
            for (int j = 0; j < 2; ++j) {
                const int nt = 2 * p + j;
                float4 hre = ex[(wg * 4 + j * 2)     * 32 + lane];
                float4 him = ex[(wg * 4 + j * 2 + 1) * 32 + lane];
                float re0 = dre[nt][0] + hre.x, im0 = dim[nt][0] + him.x;
                float re1 = dre[nt][1] + hre.y, im1 = dim[nt][1] + him.y;
                float re2 = dre[nt][2] + hre.z, im2 = dim[nt][2] + him.z;
                float re3 = dre[nt][3] + hre.w, im3 = dim[nt][3] + him.w;
                const int c = nt * 8 + 2 * qid;
                float2 w;
                w.x = z0 ? 0.0f : sqrtf(fmaf(re0, re0, im0 * im0)) * 0.015625f;
                w.y = z0 ? 0.0f : sqrtf(fmaf(re1, re1, im1 * im1)) * 0.015625f;
                *(float2*)(o0 + c) = w;
                w.x = z1 ? 0.0f : sqrtf(fmaf(re2, re2, im2 * im2)) * 0.015625f;
                w.y = z1 ? 0.0f : sqrtf(fmaf(re3, re3, im3 * im3)) * 0.015625f;
                *(float2*)(o1 + c) = w;
            }
        }
        if (p == 0) __syncthreads();
    }
}

extern "C" void kernel_launch(void* const* d_in, const int* in_sizes, int n_in,
                              void* d_out, int out_size) {
    const float* x     = (const float*)d_in[0];   // [4,4096,32]
    const float* t     = (const float*)d_in[1];   // [4,4096]
    const float* freqs = (const float*)d_in[2];   // [4096]
    float* out = (float*)d_out;                   // [4,4096,32]

    cudaFuncSetAttribute(fudft_hmma, cudaFuncAttributeMaxDynamicSharedMemorySize,
                         SMEM_TOTAL);
    fudft_hmma<<<BB * STILES, NTHREADS, SMEM_TOTAL>>>(x, t, freqs, out);
}